// round 10
// baseline (speedup 1.0000x reference)
#include <cuda_runtime.h>

#define NV 768
#define CV 256

typedef unsigned long long ull;

// Scratch (device globals: allocation-free)
__device__ float g_fin[NV * CV];        // f_input
__device__ float g_Spart[4 * NV];       // per-jblock partial S_i
__device__ float g_Lw;                  // sum of lin_w[0..255]
__device__ float g_att[NV * NV];        // leaky scores (pre-softmax)
__device__ float g_bm[12][NV];          // per-jblock row max
__device__ float g_bs[12][NV];          // per-jblock row expsum
__device__ float g_op[4][NV * CV];      // k_out split-K partials

// ---------------- packed f32x2 helpers (sm_103a) ----------------
__device__ __forceinline__ ull f32x2_add(ull a, ull b) {
    ull r; asm("add.rn.f32x2 %0, %1, %2;" : "=l"(r) : "l"(a), "l"(b)); return r;
}
__device__ __forceinline__ ull f32x2_fma(ull a, ull b, ull c) {
    ull r; asm("fma.rn.f32x2 %0, %1, %2, %3;" : "=l"(r) : "l"(a), "l"(b), "l"(c)); return r;
}
__device__ __forceinline__ ull f32x2_abs(ull a) { return a & 0x7FFFFFFF7FFFFFFFULL; }
__device__ __forceinline__ ull f32x2_dup(float v) {
    unsigned u = __float_as_uint(v); return ((ull)u << 32) | (ull)u;
}
__device__ __forceinline__ float f32x2_lo(ull a) { return __uint_as_float((unsigned)a); }
__device__ __forceinline__ float f32x2_hi(ull a) { return __uint_as_float((unsigned)(a >> 32)); }

// ---------------------------------------------------------------------------
// Kernel 0: Lw = sum lin_w[0..255]. One block. (Also makes k_out_mm the 4th
// launch so ncu's -s 5 -c 1 capture lands on it.)
// ---------------------------------------------------------------------------
__global__ void k_lw(const float* __restrict__ lin_w) {
    __shared__ float sb[128];
    const int t = threadIdx.x;   // 128
    sb[t] = lin_w[t] + lin_w[t + 128];
    __syncthreads();
    #pragma unroll
    for (int s = 64; s > 0; s >>= 1) {
        if (t < s) sb[t] += sb[t + s];
        __syncthreads();
    }
    if (t == 0) g_Lw = sb[0];
}

// ---------------------------------------------------------------------------
// Kernel 1: f_input = features @ FC (+ Spart partials).
// Tile 32(M)x64(N), 128 threads, acc[4][2]. grid (4, 24) = 96 blocks.
// ---------------------------------------------------------------------------
__global__ void k_fin(const float* __restrict__ feat, const float* __restrict__ FCm,
                      const float* __restrict__ lin_w) {
    __shared__ ull   sa2[32 * 32];   // feat pairs (8KB)
    __shared__ float sb[32 * 64];    // FC rows (8KB)

    const int tid = threadIdx.x;     // 128
    const int tx = tid & 15;
    const int ty = tid >> 4;         // 0..7
    const int j0 = blockIdx.x * 64;
    const int i0 = blockIdx.y * 32;

    ull acc[4][2];
    #pragma unroll
    for (int r = 0; r < 4; r++) { acc[r][0] = 0ull; acc[r][1] = 0ull; }

    for (int s = 0; s < 8; s++) {
        const int k0 = s * 32;
        #pragma unroll
        for (int q = 0; q < 8; q++) {
            int idx = tid + q * 128;
            sa2[idx] = f32x2_dup(feat[(i0 + (idx >> 5)) * CV + k0 + (idx & 31)]);
        }
        #pragma unroll
        for (int q = 0; q < 4; q++) {
            int i4 = tid + q * 128;
            *(float4*)&sb[(i4 >> 4) * 64 + (i4 & 15) * 4] =
                *(const float4*)&FCm[(k0 + (i4 >> 4)) * CV + j0 + (i4 & 15) * 4];
        }
        __syncthreads();

        #pragma unroll 8
        for (int kc = 0; kc < 32; kc++) {
            ull a_[4], b_[2];
            #pragma unroll
            for (int r = 0; r < 4; r++) a_[r] = sa2[(ty + 8 * r) * 32 + kc];
            #pragma unroll
            for (int m = 0; m < 2; m++) b_[m] = *(const ull*)&sb[kc * 64 + 2 * (tx + 16 * m)];
            #pragma unroll
            for (int r = 0; r < 4; r++)
                #pragma unroll
                for (int m = 0; m < 2; m++)
                    acc[r][m] = f32x2_fma(a_[r], b_[m], acc[r][m]);
        }
        __syncthreads();
    }

    const float lw00 = lin_w[j0 + 2 * tx],      lw01 = lin_w[j0 + 2 * tx + 1];
    const float lw10 = lin_w[j0 + 2 * tx + 32], lw11 = lin_w[j0 + 2 * tx + 33];

    #pragma unroll
    for (int r = 0; r < 4; r++) {
        int i = i0 + ty + 8 * r;
        #pragma unroll
        for (int m = 0; m < 2; m++)
            *(ull*)&g_fin[i * CV + j0 + 2 * (tx + 16 * m)] = acc[r][m];
        float s = f32x2_lo(acc[r][0]) * lw00 + f32x2_hi(acc[r][0]) * lw01
                + f32x2_lo(acc[r][1]) * lw10 + f32x2_hi(acc[r][1]) * lw11;
        #pragma unroll
        for (int off = 8; off > 0; off >>= 1)
            s += __shfl_down_sync(0xffffffffu, s, off, 16);
        if (tx == 0) g_Spart[blockIdx.x * NV + i] = s;
    }
}

// ---------------------------------------------------------------------------
// Kernel 2: scores + per-block softmax stats. 64x64 tile, 256 threads.
// score(i,j) = leaky( 0.6*(P_i+Q_j) + lin_b + sum_c 0.4*lw[c]*|u_i[c]+v_j[c]| )
// ---------------------------------------------------------------------------
#define SROW 258
#define SMEM_SCORES ((2 * 64 * SROW + 256 + 2 * 192 + 16) * 4)

__global__ void __launch_bounds__(256, 1) k_scores(
        const float* __restrict__ coord,
        const float* __restrict__ fc_w, const float* __restrict__ fc_b,
        const float* __restrict__ sc_w, const float* __restrict__ sc_b,
        const float* __restrict__ lin_w, const float* __restrict__ lin_b) {
    extern __shared__ float smem[];
    float* su  = smem;                        // [64][SROW]
    float* sv  = smem + 64 * SROW;            // [64][SROW]
    float* slw = smem + 2 * 64 * SROW;        // [256]
    float* scu = slw + 256;                   // [64*3]
    float* scv = scu + 192;                   // [64*3]

    const int tid = threadIdx.x;
    const int tx = tid & 15;
    const int ty = tid >> 4;
    const int i0 = blockIdx.y * 64;
    const int j0 = blockIdx.x * 64;

    const float w0 = fc_w[0], w1 = fc_w[1], bf = fc_b[0];

    {
        const int r = tid >> 2, l4 = tid & 3;
        const float4* gi = (const float4*)&g_fin[(i0 + r) * CV];
        const float4* gj = (const float4*)&g_fin[(j0 + r) * CV];
        float* sur = &su[r * SROW];
        float* svr = &sv[r * SROW];
        #pragma unroll
        for (int q = 0; q < 16; q++) {
            float4 a = gi[l4 + q * 4];
            float4 b = gj[l4 + q * 4];
            int o = (l4 + q * 4) * 4;
            sur[o]     = w0 * a.x; sur[o + 1] = w0 * a.y;
            sur[o + 2] = w0 * a.z; sur[o + 3] = w0 * a.w;
            svr[o]     = fmaf(w1, b.x, bf); svr[o + 1] = fmaf(w1, b.y, bf);
            svr[o + 2] = fmaf(w1, b.z, bf); svr[o + 3] = fmaf(w1, b.w, bf);
        }
        slw[tid] = 0.4f * lin_w[tid];
        if (tid < 192) {
            int rr = tid / 3, k = tid - rr * 3;
            scu[tid] = sc_w[0] * coord[(i0 + rr) * 3 + k];
            scv[tid] = fmaf(sc_w[1], coord[(j0 + rr) * 3 + k], sc_b[0]);
        }
    }
    __syncthreads();

    const float* sup[4];
    const float* svp[4];
    #pragma unroll
    for (int k = 0; k < 4; k++) sup[k] = &su[(ty + 16 * k) * SROW];
    #pragma unroll
    for (int m = 0; m < 4; m++) svp[m] = &sv[(tx + 16 * m) * SROW];

    ull acc[4][4];
    #pragma unroll
    for (int k = 0; k < 4; k++)
        #pragma unroll
        for (int m = 0; m < 4; m++) acc[k][m] = 0ull;

    #pragma unroll 4
    for (int cc = 0; cc < CV; cc += 2) {
        ull w2 = *(const ull*)&slw[cc];
        ull a_[4], b_[4];
        #pragma unroll
        for (int k = 0; k < 4; k++) a_[k] = *(const ull*)&sup[k][cc];
        #pragma unroll
        for (int m = 0; m < 4; m++) b_[m] = *(const ull*)&svp[m][cc];
        #pragma unroll
        for (int k = 0; k < 4; k++)
            #pragma unroll
            for (int m = 0; m < 4; m++) {
                ull t = f32x2_abs(f32x2_add(a_[k], b_[m]));
                acc[k][m] = f32x2_fma(w2, t, acc[k][m]);
            }
    }

    const float lb  = lin_b[0];
    const float Lw  = g_Lw;
    const float lc0 = lin_w[CV], lc1 = lin_w[CV + 1], lc2 = lin_w[CV + 2];
    const float base0 = fmaf(0.6f * bf, Lw, lb);

    float Si[4], Sj[4];
    #pragma unroll
    for (int k = 0; k < 4; k++) {
        int i = i0 + ty + 16 * k;
        Si[k] = (g_Spart[i] + g_Spart[NV + i]) + (g_Spart[2 * NV + i] + g_Spart[3 * NV + i]);
    }
    #pragma unroll
    for (int m = 0; m < 4; m++) {
        int j = j0 + tx + 16 * m;
        Sj[m] = (g_Spart[j] + g_Spart[NV + j]) + (g_Spart[2 * NV + j] + g_Spart[3 * NV + j]);
    }

    #pragma unroll
    for (int k = 0; k < 4; k++) {
        int ir = ty + 16 * k;
        float cu0 = scu[ir * 3], cu1 = scu[ir * 3 + 1], cu2 = scu[ir * 3 + 2];
        float val[4];
        #pragma unroll
        for (int m = 0; m < 4; m++) {
            int jr = tx + 16 * m;
            float t0 = cu0 + scv[jr * 3];
            float t1 = cu1 + scv[jr * 3 + 1];
            float t2 = cu2 + scv[jr * 3 + 2];
            float ct = lc0 * fmaf(0.4f, fabsf(t0), 0.6f * t0)
                     + lc1 * fmaf(0.4f, fabsf(t1), 0.6f * t1)
                     + lc2 * fmaf(0.4f, fabsf(t2), 0.6f * t2);
            float s = fmaf(0.6f, fmaf(w0, Si[k], w1 * Sj[m]), base0) + ct
                      + f32x2_lo(acc[k][m]) + f32x2_hi(acc[k][m]);
            val[m] = fmaxf(s, 0.2f * s);   // leaky(0.2)
            g_att[(i0 + ir) * NV + (j0 + jr)] = val[m];
        }
        float mx = fmaxf(fmaxf(val[0], val[1]), fmaxf(val[2], val[3]));
        #pragma unroll
        for (int o = 1; o < 16; o <<= 1)
            mx = fmaxf(mx, __shfl_xor_sync(0xffffffffu, mx, o));
        float se = __expf(val[0] - mx) + __expf(val[1] - mx)
                 + __expf(val[2] - mx) + __expf(val[3] - mx);
        #pragma unroll
        for (int o = 1; o < 16; o <<= 1)
            se += __shfl_xor_sync(0xffffffffu, se, o);
        if (tx == 0) {
            g_bm[blockIdx.x][i0 + ir] = mx;
            g_bs[blockIdx.x][i0 + ir] = se;
        }
    }
}

// ---------------------------------------------------------------------------
// Kernel 3: out partials = exp(scores - rowmax) @ f_input, split-K (4 ways).
// Tile 32(M)x128(N), 128 threads, acc[4][4]. grid (2, 24, 4) = 192 blocks.
// ---------------------------------------------------------------------------
__global__ void k_out_mm() {
    __shared__ ull   sa2[32 * 32];    // exp(att - m) pairs (8KB)
    __shared__ float sb[32 * 128];    // f_input rows (16KB)
    __shared__ float sm_m[32];        // row maxima

    const int tid = threadIdx.x;      // 128
    const int tx = tid & 15;
    const int ty = tid >> 4;          // 0..7
    const int j0 = blockIdx.x * 128;
    const int i0 = blockIdx.y * 32;
    const int kbase = blockIdx.z * 192;

    if (tid < 32) {
        float m = -1e30f;
        #pragma unroll
        for (int b = 0; b < 12; b++) m = fmaxf(m, g_bm[b][i0 + tid]);
        sm_m[tid] = m;
    }
    __syncthreads();

    ull acc[4][4];
    #pragma unroll
    for (int r = 0; r < 4; r++)
        #pragma unroll
        for (int m = 0; m < 4; m++) acc[r][m] = 0ull;

    for (int s = 0; s < 6; s++) {
        const int k0 = kbase + s * 32;
        #pragma unroll
        for (int q = 0; q < 8; q++) {
            int idx = tid + q * 128;
            int r = idx >> 5;
            sa2[idx] = f32x2_dup(__expf(g_att[(i0 + r) * NV + k0 + (idx & 31)] - sm_m[r]));
        }
        #pragma unroll
        for (int q = 0; q < 8; q++) {
            int i4 = tid + q * 128;
            *(float4*)&sb[(i4 >> 5) * 128 + (i4 & 31) * 4] =
                *(const float4*)&g_fin[(k0 + (i4 >> 5)) * CV + j0 + (i4 & 31) * 4];
        }
        __syncthreads();

        #pragma unroll 8
        for (int kc = 0; kc < 32; kc++) {
            ull a_[4], b_[4];
            #pragma unroll
            for (int r = 0; r < 4; r++) a_[r] = sa2[(ty + 8 * r) * 32 + kc];
            #pragma unroll
            for (int m = 0; m < 4; m++) b_[m] = *(const ull*)&sb[kc * 128 + 2 * (tx + 16 * m)];
            #pragma unroll
            for (int r = 0; r < 4; r++)
                #pragma unroll
                for (int m = 0; m < 4; m++)
                    acc[r][m] = f32x2_fma(a_[r], b_[m], acc[r][m]);
        }
        __syncthreads();
    }

    float* dst = g_op[blockIdx.z];
    #pragma unroll
    for (int r = 0; r < 4; r++) {
        int i = i0 + ty + 8 * r;
        #pragma unroll
        for (int m = 0; m < 4; m++)
            *(ull*)&dst[i * CV + j0 + 2 * (tx + 16 * m)] = acc[r][m];
    }
}

// ---------------------------------------------------------------------------
// Kernel 4: reduce 4 out partials, scale by 1/rowsum, ELU.
// grid 192, block 256; warp-per-half-row.
// ---------------------------------------------------------------------------
__global__ void k_outred(float* __restrict__ out) {
    const int g = blockIdx.x * 8 + (threadIdx.x >> 5);   // 0..1535
    const int lane = threadIdx.x & 31;
    const int row = g >> 1;
    const int col = (g & 1) * 128 + lane * 4;
    const int c0 = row * CV + col;

    // row stats (same fmax order as k_out_mm -> identical m)
    float m = -1e30f;
    #pragma unroll
    for (int b = 0; b < 12; b++) m = fmaxf(m, g_bm[b][row]);
    float ssum = 0.f;
    #pragma unroll
    for (int b = 0; b < 12; b++) ssum += g_bs[b][row] * __expf(g_bm[b][row] - m);
    const float inv = 1.0f / ssum;

    float4 s0 = make_float4(0.f, 0.f, 0.f, 0.f);
    #pragma unroll
    for (int p = 0; p < 4; p++) {
        float4 a = *(const float4*)&g_op[p][c0];
        s0.x += a.x; s0.y += a.y; s0.z += a.z; s0.w += a.w;
    }
    s0.x *= inv; s0.y *= inv; s0.z *= inv; s0.w *= inv;
    s0.x = (s0.x > 0.f) ? s0.x : (__expf(s0.x) - 1.f);
    s0.y = (s0.y > 0.f) ? s0.y : (__expf(s0.y) - 1.f);
    s0.z = (s0.z > 0.f) ? s0.z : (__expf(s0.z) - 1.f);
    s0.w = (s0.w > 0.f) ? s0.w : (__expf(s0.w) - 1.f);
    *(float4*)&out[c0] = s0;
}

// ---------------------------------------------------------------------------
extern "C" void kernel_launch(void* const* d_in, const int* in_sizes, int n_in,
                              void* d_out, int out_size) {
    const float* feat  = (const float*)d_in[0];
    const float* coord = (const float*)d_in[1];
    // d_in[2] = adj (unused by forward)
    const float* FCm   = (const float*)d_in[3];
    const float* fc_w  = (const float*)d_in[4];
    const float* fc_b  = (const float*)d_in[5];
    const float* sc_w  = (const float*)d_in[6];
    const float* sc_b  = (const float*)d_in[7];
    const float* lin_w = (const float*)d_in[8];
    const float* lin_b = (const float*)d_in[9];
    float* out = (float*)d_out;

    cudaFuncSetAttribute(k_scores, cudaFuncAttributeMaxDynamicSharedMemorySize,
                         SMEM_SCORES);

    k_lw<<<1, 128>>>(lin_w);
    k_fin<<<dim3(4, 24), 128>>>(feat, FCm, lin_w);
    k_scores<<<dim3(12, 12), 256, SMEM_SCORES>>>(coord, fc_w, fc_b, sc_w, sc_b, lin_w, lin_b);
    k_out_mm<<<dim3(2, 24, 4), 128>>>();
    k_outred<<<192, 256>>>(out);
}

// round 11
// speedup vs baseline: 1.0354x; 1.0354x over previous
#include <cuda_runtime.h>

#define NV 768
#define CV 256

typedef unsigned long long ull;

// Scratch (device globals: allocation-free)
__device__ float g_fin[NV * CV];        // f_input
__device__ float g_Spart[4 * NV];       // per-jblock partial S_i
__device__ float g_Lw;                  // sum of lin_w[0..255]
__device__ float g_att[NV * NV];        // leaky scores (pre-softmax)
__device__ float g_bm[12][NV];          // per-jblock row max
__device__ float g_bs[12][NV];          // per-jblock row expsum
__device__ float g_op[8][NV * CV];      // k_out split-K partials

// ---------------- packed f32x2 helpers (sm_103a) ----------------
__device__ __forceinline__ ull f32x2_add(ull a, ull b) {
    ull r; asm("add.rn.f32x2 %0, %1, %2;" : "=l"(r) : "l"(a), "l"(b)); return r;
}
__device__ __forceinline__ ull f32x2_fma(ull a, ull b, ull c) {
    ull r; asm("fma.rn.f32x2 %0, %1, %2, %3;" : "=l"(r) : "l"(a), "l"(b), "l"(c)); return r;
}
__device__ __forceinline__ ull f32x2_abs(ull a) { return a & 0x7FFFFFFF7FFFFFFFULL; }
__device__ __forceinline__ ull f32x2_dup(float v) {
    unsigned u = __float_as_uint(v); return ((ull)u << 32) | (ull)u;
}
__device__ __forceinline__ float f32x2_lo(ull a) { return __uint_as_float((unsigned)a); }
__device__ __forceinline__ float f32x2_hi(ull a) { return __uint_as_float((unsigned)(a >> 32)); }

// ---------------------------------------------------------------------------
// Kernel 0: Lw = sum lin_w[0..255]. One block. (Also keeps ncu's -s 5 -c 1
// capture landing on k_out_mm as the 4th launch.)
// ---------------------------------------------------------------------------
__global__ void k_lw(const float* __restrict__ lin_w) {
    __shared__ float sb[128];
    const int t = threadIdx.x;   // 128
    sb[t] = lin_w[t] + lin_w[t + 128];
    __syncthreads();
    #pragma unroll
    for (int s = 64; s > 0; s >>= 1) {
        if (t < s) sb[t] += sb[t + s];
        __syncthreads();
    }
    if (t == 0) g_Lw = sb[0];
}

// ---------------------------------------------------------------------------
// Kernel 1: f_input = features @ FC (+ Spart partials).
// Tile 32(M)x64(N), 128 threads, acc[4][2]. grid (4, 24) = 96 blocks.
// ---------------------------------------------------------------------------
__global__ void k_fin(const float* __restrict__ feat, const float* __restrict__ FCm,
                      const float* __restrict__ lin_w) {
    __shared__ ull   sa2[32 * 32];   // feat pairs (8KB)
    __shared__ float sb[32 * 64];    // FC rows (8KB)

    const int tid = threadIdx.x;     // 128
    const int tx = tid & 15;
    const int ty = tid >> 4;         // 0..7
    const int j0 = blockIdx.x * 64;
    const int i0 = blockIdx.y * 32;

    ull acc[4][2];
    #pragma unroll
    for (int r = 0; r < 4; r++) { acc[r][0] = 0ull; acc[r][1] = 0ull; }

    for (int s = 0; s < 8; s++) {
        const int k0 = s * 32;
        #pragma unroll
        for (int q = 0; q < 8; q++) {
            int idx = tid + q * 128;
            sa2[idx] = f32x2_dup(feat[(i0 + (idx >> 5)) * CV + k0 + (idx & 31)]);
        }
        #pragma unroll
        for (int q = 0; q < 4; q++) {
            int i4 = tid + q * 128;
            *(float4*)&sb[(i4 >> 4) * 64 + (i4 & 15) * 4] =
                *(const float4*)&FCm[(k0 + (i4 >> 4)) * CV + j0 + (i4 & 15) * 4];
        }
        __syncthreads();

        #pragma unroll 8
        for (int kc = 0; kc < 32; kc++) {
            ull a_[4], b_[2];
            #pragma unroll
            for (int r = 0; r < 4; r++) a_[r] = sa2[(ty + 8 * r) * 32 + kc];
            #pragma unroll
            for (int m = 0; m < 2; m++) b_[m] = *(const ull*)&sb[kc * 64 + 2 * (tx + 16 * m)];
            #pragma unroll
            for (int r = 0; r < 4; r++)
                #pragma unroll
                for (int m = 0; m < 2; m++)
                    acc[r][m] = f32x2_fma(a_[r], b_[m], acc[r][m]);
        }
        __syncthreads();
    }

    const float lw00 = lin_w[j0 + 2 * tx],      lw01 = lin_w[j0 + 2 * tx + 1];
    const float lw10 = lin_w[j0 + 2 * tx + 32], lw11 = lin_w[j0 + 2 * tx + 33];

    #pragma unroll
    for (int r = 0; r < 4; r++) {
        int i = i0 + ty + 8 * r;
        #pragma unroll
        for (int m = 0; m < 2; m++)
            *(ull*)&g_fin[i * CV + j0 + 2 * (tx + 16 * m)] = acc[r][m];
        float s = f32x2_lo(acc[r][0]) * lw00 + f32x2_hi(acc[r][0]) * lw01
                + f32x2_lo(acc[r][1]) * lw10 + f32x2_hi(acc[r][1]) * lw11;
        #pragma unroll
        for (int off = 8; off > 0; off >>= 1)
            s += __shfl_down_sync(0xffffffffu, s, off, 16);
        if (tx == 0) g_Spart[blockIdx.x * NV + i] = s;
    }
}

// ---------------------------------------------------------------------------
// Kernel 2: scores + per-block softmax stats. 64x64 tile, 256 threads.
// score(i,j) = leaky( 0.6*(P_i+Q_j) + lin_b + sum_c 0.4*lw[c]*|u_i[c]+v_j[c]| )
// ---------------------------------------------------------------------------
#define SROW 258
#define SMEM_SCORES ((2 * 64 * SROW + 256 + 2 * 192 + 16) * 4)

__global__ void __launch_bounds__(256, 1) k_scores(
        const float* __restrict__ coord,
        const float* __restrict__ fc_w, const float* __restrict__ fc_b,
        const float* __restrict__ sc_w, const float* __restrict__ sc_b,
        const float* __restrict__ lin_w, const float* __restrict__ lin_b) {
    extern __shared__ float smem[];
    float* su  = smem;                        // [64][SROW]
    float* sv  = smem + 64 * SROW;            // [64][SROW]
    float* slw = smem + 2 * 64 * SROW;        // [256]
    float* scu = slw + 256;                   // [64*3]
    float* scv = scu + 192;                   // [64*3]

    const int tid = threadIdx.x;
    const int tx = tid & 15;
    const int ty = tid >> 4;
    const int i0 = blockIdx.y * 64;
    const int j0 = blockIdx.x * 64;

    const float w0 = fc_w[0], w1 = fc_w[1], bf = fc_b[0];

    {
        const int r = tid >> 2, l4 = tid & 3;
        const float4* gi = (const float4*)&g_fin[(i0 + r) * CV];
        const float4* gj = (const float4*)&g_fin[(j0 + r) * CV];
        float* sur = &su[r * SROW];
        float* svr = &sv[r * SROW];
        #pragma unroll
        for (int q = 0; q < 16; q++) {
            float4 a = gi[l4 + q * 4];
            float4 b = gj[l4 + q * 4];
            int o = (l4 + q * 4) * 4;
            sur[o]     = w0 * a.x; sur[o + 1] = w0 * a.y;
            sur[o + 2] = w0 * a.z; sur[o + 3] = w0 * a.w;
            svr[o]     = fmaf(w1, b.x, bf); svr[o + 1] = fmaf(w1, b.y, bf);
            svr[o + 2] = fmaf(w1, b.z, bf); svr[o + 3] = fmaf(w1, b.w, bf);
        }
        slw[tid] = 0.4f * lin_w[tid];
        if (tid < 192) {
            int rr = tid / 3, k = tid - rr * 3;
            scu[tid] = sc_w[0] * coord[(i0 + rr) * 3 + k];
            scv[tid] = fmaf(sc_w[1], coord[(j0 + rr) * 3 + k], sc_b[0]);
        }
    }
    __syncthreads();

    const float* sup[4];
    const float* svp[4];
    #pragma unroll
    for (int k = 0; k < 4; k++) sup[k] = &su[(ty + 16 * k) * SROW];
    #pragma unroll
    for (int m = 0; m < 4; m++) svp[m] = &sv[(tx + 16 * m) * SROW];

    ull acc[4][4];
    #pragma unroll
    for (int k = 0; k < 4; k++)
        #pragma unroll
        for (int m = 0; m < 4; m++) acc[k][m] = 0ull;

    #pragma unroll 4
    for (int cc = 0; cc < CV; cc += 2) {
        ull w2 = *(const ull*)&slw[cc];
        ull a_[4], b_[4];
        #pragma unroll
        for (int k = 0; k < 4; k++) a_[k] = *(const ull*)&sup[k][cc];
        #pragma unroll
        for (int m = 0; m < 4; m++) b_[m] = *(const ull*)&svp[m][cc];
        #pragma unroll
        for (int k = 0; k < 4; k++)
            #pragma unroll
            for (int m = 0; m < 4; m++) {
                ull t = f32x2_abs(f32x2_add(a_[k], b_[m]));
                acc[k][m] = f32x2_fma(w2, t, acc[k][m]);
            }
    }

    const float lb  = lin_b[0];
    const float Lw  = g_Lw;
    const float lc0 = lin_w[CV], lc1 = lin_w[CV + 1], lc2 = lin_w[CV + 2];
    const float base0 = fmaf(0.6f * bf, Lw, lb);

    float Si[4], Sj[4];
    #pragma unroll
    for (int k = 0; k < 4; k++) {
        int i = i0 + ty + 16 * k;
        Si[k] = (g_Spart[i] + g_Spart[NV + i]) + (g_Spart[2 * NV + i] + g_Spart[3 * NV + i]);
    }
    #pragma unroll
    for (int m = 0; m < 4; m++) {
        int j = j0 + tx + 16 * m;
        Sj[m] = (g_Spart[j] + g_Spart[NV + j]) + (g_Spart[2 * NV + j] + g_Spart[3 * NV + j]);
    }

    #pragma unroll
    for (int k = 0; k < 4; k++) {
        int ir = ty + 16 * k;
        float cu0 = scu[ir * 3], cu1 = scu[ir * 3 + 1], cu2 = scu[ir * 3 + 2];
        float val[4];
        #pragma unroll
        for (int m = 0; m < 4; m++) {
            int jr = tx + 16 * m;
            float t0 = cu0 + scv[jr * 3];
            float t1 = cu1 + scv[jr * 3 + 1];
            float t2 = cu2 + scv[jr * 3 + 2];
            float ct = lc0 * fmaf(0.4f, fabsf(t0), 0.6f * t0)
                     + lc1 * fmaf(0.4f, fabsf(t1), 0.6f * t1)
                     + lc2 * fmaf(0.4f, fabsf(t2), 0.6f * t2);
            float s = fmaf(0.6f, fmaf(w0, Si[k], w1 * Sj[m]), base0) + ct
                      + f32x2_lo(acc[k][m]) + f32x2_hi(acc[k][m]);
            val[m] = fmaxf(s, 0.2f * s);   // leaky(0.2)
            g_att[(i0 + ir) * NV + (j0 + jr)] = val[m];
        }
        float mx = fmaxf(fmaxf(val[0], val[1]), fmaxf(val[2], val[3]));
        #pragma unroll
        for (int o = 1; o < 16; o <<= 1)
            mx = fmaxf(mx, __shfl_xor_sync(0xffffffffu, mx, o));
        float se = __expf(val[0] - mx) + __expf(val[1] - mx)
                 + __expf(val[2] - mx) + __expf(val[3] - mx);
        #pragma unroll
        for (int o = 1; o < 16; o <<= 1)
            se += __shfl_xor_sync(0xffffffffu, se, o);
        if (tx == 0) {
            g_bm[blockIdx.x][i0 + ir] = mx;
            g_bs[blockIdx.x][i0 + ir] = se;
        }
    }
}

// ---------------------------------------------------------------------------
// Kernel 3: out partials = exp(scores - rowmax) @ f_input, split-K (8 ways).
// Tile 32(M)x128(N), 256 threads (8 warps), acc[2][4].
// grid (2, 24, 8) = 384 blocks -> ~5 warps/SMSP for latency hiding.
// ---------------------------------------------------------------------------
__global__ void __launch_bounds__(256) k_out_mm() {
    __shared__ ull   sa2[32 * 32];    // exp(att - m) pairs (8KB)
    __shared__ float sb[32 * 128];    // f_input rows (16KB)
    __shared__ float sm_m[32];        // row maxima

    const int tid = threadIdx.x;      // 256
    const int tx = tid & 15;
    const int ty = tid >> 4;          // 0..15
    const int j0 = blockIdx.x * 128;
    const int i0 = blockIdx.y * 32;
    const int kbase = blockIdx.z * 96;

    if (tid < 32) {
        float m = -1e30f;
        #pragma unroll
        for (int b = 0; b < 12; b++) m = fmaxf(m, g_bm[b][i0 + tid]);
        sm_m[tid] = m;
    }
    __syncthreads();

    ull acc[2][4];
    #pragma unroll
    for (int r = 0; r < 2; r++)
        #pragma unroll
        for (int m = 0; m < 4; m++) acc[r][m] = 0ull;

    for (int s = 0; s < 3; s++) {
        const int k0 = kbase + s * 32;
        #pragma unroll
        for (int q = 0; q < 4; q++) {
            int idx = tid + q * 256;           // 0..1023
            int r = idx >> 5;
            sa2[idx] = f32x2_dup(__expf(g_att[(i0 + r) * NV + k0 + (idx & 31)] - sm_m[r]));
        }
        #pragma unroll
        for (int q = 0; q < 4; q++) {
            int i4 = tid + q * 256;            // 0..1023 float4s
            *(float4*)&sb[(i4 >> 5) * 128 + (i4 & 31) * 4] =
                *(const float4*)&g_fin[(k0 + (i4 >> 5)) * CV + j0 + (i4 & 31) * 4];
        }
        __syncthreads();

        #pragma unroll 8
        for (int kc = 0; kc < 32; kc++) {
            ull a_[2], b_[4];
            #pragma unroll
            for (int r = 0; r < 2; r++) a_[r] = sa2[(ty + 16 * r) * 32 + kc];
            #pragma unroll
            for (int m = 0; m < 4; m++) b_[m] = *(const ull*)&sb[kc * 128 + 2 * (tx + 16 * m)];
            #pragma unroll
            for (int r = 0; r < 2; r++)
                #pragma unroll
                for (int m = 0; m < 4; m++)
                    acc[r][m] = f32x2_fma(a_[r], b_[m], acc[r][m]);
        }
        __syncthreads();
    }

    float* dst = g_op[blockIdx.z];
    #pragma unroll
    for (int r = 0; r < 2; r++) {
        int i = i0 + ty + 16 * r;
        #pragma unroll
        for (int m = 0; m < 4; m++)
            *(ull*)&dst[i * CV + j0 + 2 * (tx + 16 * m)] = acc[r][m];
    }
}

// ---------------------------------------------------------------------------
// Kernel 4: reduce 8 out partials, scale by 1/rowsum, ELU.
// grid 192, block 256; warp-per-half-row.
// ---------------------------------------------------------------------------
__global__ void k_outred(float* __restrict__ out) {
    const int g = blockIdx.x * 8 + (threadIdx.x >> 5);   // 0..1535
    const int lane = threadIdx.x & 31;
    const int row = g >> 1;
    const int col = (g & 1) * 128 + lane * 4;
    const int c0 = row * CV + col;

    // row stats (same fmax order as k_out_mm -> identical m)
    float m = -1e30f;
    #pragma unroll
    for (int b = 0; b < 12; b++) m = fmaxf(m, g_bm[b][row]);
    float ssum = 0.f;
    #pragma unroll
    for (int b = 0; b < 12; b++) ssum += g_bs[b][row] * __expf(g_bm[b][row] - m);
    const float inv = 1.0f / ssum;

    float4 s0 = make_float4(0.f, 0.f, 0.f, 0.f);
    #pragma unroll
    for (int p = 0; p < 8; p++) {
        float4 a = *(const float4*)&g_op[p][c0];
        s0.x += a.x; s0.y += a.y; s0.z += a.z; s0.w += a.w;
    }
    s0.x *= inv; s0.y *= inv; s0.z *= inv; s0.w *= inv;
    s0.x = (s0.x > 0.f) ? s0.x : (__expf(s0.x) - 1.f);
    s0.y = (s0.y > 0.f) ? s0.y : (__expf(s0.y) - 1.f);
    s0.z = (s0.z > 0.f) ? s0.z : (__expf(s0.z) - 1.f);
    s0.w = (s0.w > 0.f) ? s0.w : (__expf(s0.w) - 1.f);
    *(float4*)&out[c0] = s0;
}

// ---------------------------------------------------------------------------
extern "C" void kernel_launch(void* const* d_in, const int* in_sizes, int n_in,
                              void* d_out, int out_size) {
    const float* feat  = (const float*)d_in[0];
    const float* coord = (const float*)d_in[1];
    // d_in[2] = adj (unused by forward)
    const float* FCm   = (const float*)d_in[3];
    const float* fc_w  = (const float*)d_in[4];
    const float* fc_b  = (const float*)d_in[5];
    const float* sc_w  = (const float*)d_in[6];
    const float* sc_b  = (const float*)d_in[7];
    const float* lin_w = (const float*)d_in[8];
    const float* lin_b = (const float*)d_in[9];
    float* out = (float*)d_out;

    cudaFuncSetAttribute(k_scores, cudaFuncAttributeMaxDynamicSharedMemorySize,
                         SMEM_SCORES);

    k_lw<<<1, 128>>>(lin_w);
    k_fin<<<dim3(4, 24), 128>>>(feat, FCm, lin_w);
    k_scores<<<dim3(12, 12), 256, SMEM_SCORES>>>(coord, fc_w, fc_b, sc_w, sc_b, lin_w, lin_b);
    k_out_mm<<<dim3(2, 24, 8), 256>>>();
    k_outred<<<192, 256>>>(out);
}

// round 12
// speedup vs baseline: 1.1103x; 1.0724x over previous
#include <cuda_runtime.h>

#define NV 768
#define CV 256

typedef unsigned long long ull;

// Scratch (device globals: allocation-free)
__device__ float g_fin[NV * CV];        // f_input
__device__ float g_Spart[4 * NV];       // per-jblock partial S_i
__device__ float g_Lw;                  // sum of lin_w[0..255]
__device__ float g_cu[NV * 3];          // sc_w0 * coord
__device__ float g_cv[NV * 3];          // sc_w1 * coord + sc_b
__device__ float g_att[NV * NV];        // leaky scores (pre-softmax)
__device__ float g_bm[12][NV];          // per-jblock row max
__device__ float g_bs[12][NV];          // per-jblock row expsum
__device__ float g_op[8][NV * CV];      // k_out split-K partials

// ---------------- packed f32x2 helpers (sm_103a) ----------------
__device__ __forceinline__ ull f32x2_add(ull a, ull b) {
    ull r; asm("add.rn.f32x2 %0, %1, %2;" : "=l"(r) : "l"(a), "l"(b)); return r;
}
__device__ __forceinline__ ull f32x2_fma(ull a, ull b, ull c) {
    ull r; asm("fma.rn.f32x2 %0, %1, %2, %3;" : "=l"(r) : "l"(a), "l"(b), "l"(c)); return r;
}
__device__ __forceinline__ ull f32x2_abs(ull a) { return a & 0x7FFFFFFF7FFFFFFFULL; }
__device__ __forceinline__ ull f32x2_dup(float v) {
    unsigned u = __float_as_uint(v); return ((ull)u << 32) | (ull)u;
}
__device__ __forceinline__ float f32x2_lo(ull a) { return __uint_as_float((unsigned)a); }
__device__ __forceinline__ float f32x2_hi(ull a) { return __uint_as_float((unsigned)(a >> 32)); }

// ---------------------------------------------------------------------------
// Kernel 0a: Lw = sum lin_w[0..255]. One block.
// ---------------------------------------------------------------------------
__global__ void k_lw(const float* __restrict__ lin_w) {
    __shared__ float sb[128];
    const int t = threadIdx.x;   // 128
    sb[t] = lin_w[t] + lin_w[t + 128];
    __syncthreads();
    #pragma unroll
    for (int s = 64; s > 0; s >>= 1) {
        if (t < s) sb[t] += sb[t + s];
        __syncthreads();
    }
    if (t == 0) g_Lw = sb[0];
}

// ---------------------------------------------------------------------------
// Kernel 0b: coordinate preprocessing (also positions k_scores as 4th launch
// so ncu's capture lands on it). grid 9 x 256.
// ---------------------------------------------------------------------------
__global__ void k_coordprep(const float* __restrict__ coord,
                            const float* __restrict__ sc_w,
                            const float* __restrict__ sc_b) {
    const int idx = blockIdx.x * 256 + threadIdx.x;
    if (idx < NV * 3) {
        float c = coord[idx];
        g_cu[idx] = sc_w[0] * c;
        g_cv[idx] = fmaf(sc_w[1], c, sc_b[0]);
    }
}

// ---------------------------------------------------------------------------
// Kernel 1: f_input = features @ FC (+ Spart partials).
// Tile 32(M)x64(N), 128 threads, acc[4][2]. grid (4, 24) = 96 blocks.
// ---------------------------------------------------------------------------
__global__ void k_fin(const float* __restrict__ feat, const float* __restrict__ FCm,
                      const float* __restrict__ lin_w) {
    __shared__ ull   sa2[32 * 32];   // feat pairs (8KB)
    __shared__ float sb[32 * 64];    // FC rows (8KB)

    const int tid = threadIdx.x;     // 128
    const int tx = tid & 15;
    const int ty = tid >> 4;         // 0..7
    const int j0 = blockIdx.x * 64;
    const int i0 = blockIdx.y * 32;

    ull acc[4][2];
    #pragma unroll
    for (int r = 0; r < 4; r++) { acc[r][0] = 0ull; acc[r][1] = 0ull; }

    for (int s = 0; s < 8; s++) {
        const int k0 = s * 32;
        #pragma unroll
        for (int q = 0; q < 8; q++) {
            int idx = tid + q * 128;
            sa2[idx] = f32x2_dup(feat[(i0 + (idx >> 5)) * CV + k0 + (idx & 31)]);
        }
        #pragma unroll
        for (int q = 0; q < 4; q++) {
            int i4 = tid + q * 128;
            *(float4*)&sb[(i4 >> 4) * 64 + (i4 & 15) * 4] =
                *(const float4*)&FCm[(k0 + (i4 >> 4)) * CV + j0 + (i4 & 15) * 4];
        }
        __syncthreads();

        #pragma unroll 8
        for (int kc = 0; kc < 32; kc++) {
            ull a_[4], b_[2];
            #pragma unroll
            for (int r = 0; r < 4; r++) a_[r] = sa2[(ty + 8 * r) * 32 + kc];
            #pragma unroll
            for (int m = 0; m < 2; m++) b_[m] = *(const ull*)&sb[kc * 64 + 2 * (tx + 16 * m)];
            #pragma unroll
            for (int r = 0; r < 4; r++)
                #pragma unroll
                for (int m = 0; m < 2; m++)
                    acc[r][m] = f32x2_fma(a_[r], b_[m], acc[r][m]);
        }
        __syncthreads();
    }

    const float lw00 = lin_w[j0 + 2 * tx],      lw01 = lin_w[j0 + 2 * tx + 1];
    const float lw10 = lin_w[j0 + 2 * tx + 32], lw11 = lin_w[j0 + 2 * tx + 33];

    #pragma unroll
    for (int r = 0; r < 4; r++) {
        int i = i0 + ty + 8 * r;
        #pragma unroll
        for (int m = 0; m < 2; m++)
            *(ull*)&g_fin[i * CV + j0 + 2 * (tx + 16 * m)] = acc[r][m];
        float s = f32x2_lo(acc[r][0]) * lw00 + f32x2_hi(acc[r][0]) * lw01
                + f32x2_lo(acc[r][1]) * lw10 + f32x2_hi(acc[r][1]) * lw11;
        #pragma unroll
        for (int off = 8; off > 0; off >>= 1)
            s += __shfl_down_sync(0xffffffffu, s, off, 16);
        if (tx == 0) g_Spart[blockIdx.x * NV + i] = s;
    }
}

// ---------------------------------------------------------------------------
// Kernel 2: scores + per-block softmax stats. 64x64 tile, 512 threads (16
// warps = 4/SMSP for latency hiding), acc[2][4] micro-tile.
// score(i,j) = leaky( 0.6*(P_i+Q_j) + lin_b + sum_c 0.4*lw[c]*|u_i[c]+v_j[c]| )
// ---------------------------------------------------------------------------
#define SROW 258
#define SMEM_SCORES ((2 * 64 * SROW + 256 + 2 * 192 + 16) * 4)

__global__ void __launch_bounds__(512, 1) k_scores(
        const float* __restrict__ fc_w, const float* __restrict__ fc_b,
        const float* __restrict__ lin_w, const float* __restrict__ lin_b) {
    extern __shared__ float smem[];
    float* su  = smem;                        // [64][SROW]
    float* sv  = smem + 64 * SROW;            // [64][SROW]
    float* slw = smem + 2 * 64 * SROW;        // [256]
    float* scu = slw + 256;                   // [64*3]
    float* scv = scu + 192;                   // [64*3]

    const int tid = threadIdx.x;   // 0..511
    const int tx = tid & 15;
    const int ty = tid >> 4;       // 0..31
    const int i0 = blockIdx.y * 64;
    const int j0 = blockIdx.x * 64;

    const float w0 = fc_w[0], w1 = fc_w[1], bf = fc_b[0];

    // Fill: each thread writes half a row of su and sv (8 float4 chunks).
    {
        const int r = tid >> 3, l8 = tid & 7;
        const float4* gi = (const float4*)&g_fin[(i0 + r) * CV];
        const float4* gj = (const float4*)&g_fin[(j0 + r) * CV];
        float* sur = &su[r * SROW];
        float* svr = &sv[r * SROW];
        #pragma unroll
        for (int q = 0; q < 8; q++) {
            int c4 = l8 + q * 8;               // 0..63
            float4 a = gi[c4];
            float4 b = gj[c4];
            int o = c4 * 4;
            sur[o]     = w0 * a.x; sur[o + 1] = w0 * a.y;
            sur[o + 2] = w0 * a.z; sur[o + 3] = w0 * a.w;
            svr[o]     = fmaf(w1, b.x, bf); svr[o + 1] = fmaf(w1, b.y, bf);
            svr[o + 2] = fmaf(w1, b.z, bf); svr[o + 3] = fmaf(w1, b.w, bf);
        }
        if (tid < 256) slw[tid] = 0.4f * lin_w[tid];
        if (tid < 192) {
            scu[tid] = g_cu[i0 * 3 + tid];
            scv[tid] = g_cv[j0 * 3 + tid];
        }
    }
    __syncthreads();

    const float* sup[2];
    const float* svp[4];
    #pragma unroll
    for (int k = 0; k < 2; k++) sup[k] = &su[(ty + 32 * k) * SROW];
    #pragma unroll
    for (int m = 0; m < 4; m++) svp[m] = &sv[(tx + 16 * m) * SROW];

    ull acc[2][4];
    #pragma unroll
    for (int k = 0; k < 2; k++)
        #pragma unroll
        for (int m = 0; m < 4; m++) acc[k][m] = 0ull;

    #pragma unroll 4
    for (int cc = 0; cc < CV; cc += 2) {
        ull w2 = *(const ull*)&slw[cc];
        ull a_[2], b_[4];
        #pragma unroll
        for (int k = 0; k < 2; k++) a_[k] = *(const ull*)&sup[k][cc];
        #pragma unroll
        for (int m = 0; m < 4; m++) b_[m] = *(const ull*)&svp[m][cc];
        #pragma unroll
        for (int k = 0; k < 2; k++)
            #pragma unroll
            for (int m = 0; m < 4; m++) {
                ull t = f32x2_abs(f32x2_add(a_[k], b_[m]));
                acc[k][m] = f32x2_fma(w2, t, acc[k][m]);
            }
    }

    const float lb  = lin_b[0];
    const float Lw  = g_Lw;
    const float lc0 = lin_w[CV], lc1 = lin_w[CV + 1], lc2 = lin_w[CV + 2];
    const float base0 = fmaf(0.6f * bf, Lw, lb);

    float Si[2], Sj[4];
    #pragma unroll
    for (int k = 0; k < 2; k++) {
        int i = i0 + ty + 32 * k;
        Si[k] = (g_Spart[i] + g_Spart[NV + i]) + (g_Spart[2 * NV + i] + g_Spart[3 * NV + i]);
    }
    #pragma unroll
    for (int m = 0; m < 4; m++) {
        int j = j0 + tx + 16 * m;
        Sj[m] = (g_Spart[j] + g_Spart[NV + j]) + (g_Spart[2 * NV + j] + g_Spart[3 * NV + j]);
    }

    #pragma unroll
    for (int k = 0; k < 2; k++) {
        int ir = ty + 32 * k;
        float cu0 = scu[ir * 3], cu1 = scu[ir * 3 + 1], cu2 = scu[ir * 3 + 2];
        float val[4];
        #pragma unroll
        for (int m = 0; m < 4; m++) {
            int jr = tx + 16 * m;
            float t0 = cu0 + scv[jr * 3];
            float t1 = cu1 + scv[jr * 3 + 1];
            float t2 = cu2 + scv[jr * 3 + 2];
            float ct = lc0 * fmaf(0.4f, fabsf(t0), 0.6f * t0)
                     + lc1 * fmaf(0.4f, fabsf(t1), 0.6f * t1)
                     + lc2 * fmaf(0.4f, fabsf(t2), 0.6f * t2);
            float s = fmaf(0.6f, fmaf(w0, Si[k], w1 * Sj[m]), base0) + ct
                      + f32x2_lo(acc[k][m]) + f32x2_hi(acc[k][m]);
            val[m] = fmaxf(s, 0.2f * s);   // leaky(0.2)
            g_att[(i0 + ir) * NV + (j0 + jr)] = val[m];
        }
        // per-row stats over this block's 64 cols (16-lane shuffle group)
        float mx = fmaxf(fmaxf(val[0], val[1]), fmaxf(val[2], val[3]));
        #pragma unroll
        for (int o = 1; o < 16; o <<= 1)
            mx = fmaxf(mx, __shfl_xor_sync(0xffffffffu, mx, o));
        float se = __expf(val[0] - mx) + __expf(val[1] - mx)
                 + __expf(val[2] - mx) + __expf(val[3] - mx);
        #pragma unroll
        for (int o = 1; o < 16; o <<= 1)
            se += __shfl_xor_sync(0xffffffffu, se, o);
        if (tx == 0) {
            g_bm[blockIdx.x][i0 + ir] = mx;
            g_bs[blockIdx.x][i0 + ir] = se;
        }
    }
}

// ---------------------------------------------------------------------------
// Kernel 3: out partials = exp(scores - rowmax) @ f_input, split-K (8 ways).
// Tile 32(M)x128(N), 128 threads, acc[4][4]. grid (2, 24, 8) = 384 blocks.
// (R8 config — proven fastest.)
// ---------------------------------------------------------------------------
__global__ void k_out_mm() {
    __shared__ ull   sa2[32 * 32];    // exp(att - m) pairs (8KB)
    __shared__ float sb[32 * 128];    // f_input rows (16KB)
    __shared__ float sm_m[32];        // row maxima

    const int tid = threadIdx.x;      // 128
    const int tx = tid & 15;
    const int ty = tid >> 4;          // 0..7
    const int j0 = blockIdx.x * 128;
    const int i0 = blockIdx.y * 32;
    const int kbase = blockIdx.z * 96;

    if (tid < 32) {
        float m = -1e30f;
        #pragma unroll
        for (int b = 0; b < 12; b++) m = fmaxf(m, g_bm[b][i0 + tid]);
        sm_m[tid] = m;
    }
    __syncthreads();

    ull acc[4][4];
    #pragma unroll
    for (int r = 0; r < 4; r++)
        #pragma unroll
        for (int m = 0; m < 4; m++) acc[r][m] = 0ull;

    for (int s = 0; s < 3; s++) {
        const int k0 = kbase + s * 32;
        #pragma unroll
        for (int q = 0; q < 8; q++) {
            int idx = tid + q * 128;
            int r = idx >> 5;
            sa2[idx] = f32x2_dup(__expf(g_att[(i0 + r) * NV + k0 + (idx & 31)] - sm_m[r]));
        }
        #pragma unroll
        for (int q = 0; q < 8; q++) {
            int i4 = tid + q * 128;
            *(float4*)&sb[(i4 >> 5) * 128 + (i4 & 31) * 4] =
                *(const float4*)&g_fin[(k0 + (i4 >> 5)) * CV + j0 + (i4 & 31) * 4];
        }
        __syncthreads();

        #pragma unroll 8
        for (int kc = 0; kc < 32; kc++) {
            ull a_[4], b_[4];
            #pragma unroll
            for (int r = 0; r < 4; r++) a_[r] = sa2[(ty + 8 * r) * 32 + kc];
            #pragma unroll
            for (int m = 0; m < 4; m++) b_[m] = *(const ull*)&sb[kc * 128 + 2 * (tx + 16 * m)];
            #pragma unroll
            for (int r = 0; r < 4; r++)
                #pragma unroll
                for (int m = 0; m < 4; m++)
                    acc[r][m] = f32x2_fma(a_[r], b_[m], acc[r][m]);
        }
        __syncthreads();
    }

    float* dst = g_op[blockIdx.z];
    #pragma unroll
    for (int r = 0; r < 4; r++) {
        int i = i0 + ty + 8 * r;
        #pragma unroll
        for (int m = 0; m < 4; m++)
            *(ull*)&dst[i * CV + j0 + 2 * (tx + 16 * m)] = acc[r][m];
    }
}

// ---------------------------------------------------------------------------
// Kernel 4: reduce 8 out partials, scale by 1/rowsum, ELU.
// grid 192, block 256; warp-per-half-row.
// ---------------------------------------------------------------------------
__global__ void k_outred(float* __restrict__ out) {
    const int g = blockIdx.x * 8 + (threadIdx.x >> 5);   // 0..1535
    const int lane = threadIdx.x & 31;
    const int row = g >> 1;
    const int col = (g & 1) * 128 + lane * 4;
    const int c0 = row * CV + col;

    // row stats (same fmax order as k_out_mm -> identical m)
    float m = -1e30f;
    #pragma unroll
    for (int b = 0; b < 12; b++) m = fmaxf(m, g_bm[b][row]);
    float ssum = 0.f;
    #pragma unroll
    for (int b = 0; b < 12; b++) ssum += g_bs[b][row] * __expf(g_bm[b][row] - m);
    const float inv = 1.0f / ssum;

    float4 s0 = make_float4(0.f, 0.f, 0.f, 0.f);
    #pragma unroll
    for (int p = 0; p < 8; p++) {
        float4 a = *(const float4*)&g_op[p][c0];
        s0.x += a.x; s0.y += a.y; s0.z += a.z; s0.w += a.w;
    }
    s0.x *= inv; s0.y *= inv; s0.z *= inv; s0.w *= inv;
    s0.x = (s0.x > 0.f) ? s0.x : (__expf(s0.x) - 1.f);
    s0.y = (s0.y > 0.f) ? s0.y : (__expf(s0.y) - 1.f);
    s0.z = (s0.z > 0.f) ? s0.z : (__expf(s0.z) - 1.f);
    s0.w = (s0.w > 0.f) ? s0.w : (__expf(s0.w) - 1.f);
    *(float4*)&out[c0] = s0;
}

// ---------------------------------------------------------------------------
extern "C" void kernel_launch(void* const* d_in, const int* in_sizes, int n_in,
                              void* d_out, int out_size) {
    const float* feat  = (const float*)d_in[0];
    const float* coord = (const float*)d_in[1];
    // d_in[2] = adj (unused by forward)
    const float* FCm   = (const float*)d_in[3];
    const float* fc_w  = (const float*)d_in[4];
    const float* fc_b  = (const float*)d_in[5];
    const float* sc_w  = (const float*)d_in[6];
    const float* sc_b  = (const float*)d_in[7];
    const float* lin_w = (const float*)d_in[8];
    const float* lin_b = (const float*)d_in[9];
    float* out = (float*)d_out;

    cudaFuncSetAttribute(k_scores, cudaFuncAttributeMaxDynamicSharedMemorySize,
                         SMEM_SCORES);

    k_lw<<<1, 128>>>(lin_w);
    k_coordprep<<<9, 256>>>(coord, sc_w, sc_b);
    k_fin<<<dim3(4, 24), 128>>>(feat, FCm, lin_w);
    k_scores<<<dim3(12, 12), 512, SMEM_SCORES>>>(fc_w, fc_b, lin_w, lin_b);
    k_out_mm<<<dim3(2, 24, 8), 128>>>();
    k_outred<<<192, 256>>>(out);
}

// round 13
// speedup vs baseline: 1.2062x; 1.0863x over previous
#include <cuda_runtime.h>

#define NV 768
#define CV 256

typedef unsigned long long ull;

// Scratch (device globals: allocation-free)
__device__ float g_fin[NV * CV];        // f_input
__device__ float g_Spart[4 * NV];       // per-jblock partial S_i
__device__ float g_Lw;                  // sum of lin_w[0..255]
__device__ float g_att[NV * NV];        // leaky scores (pre-softmax)
__device__ float g_bm[12][NV];          // per-jblock row max
__device__ float g_bs[12][NV];          // per-jblock row expsum
__device__ float g_op[8][NV * CV];      // k_out split-K partials

// ---------------- packed f32x2 helpers (sm_103a) ----------------
__device__ __forceinline__ ull f32x2_add(ull a, ull b) {
    ull r; asm("add.rn.f32x2 %0, %1, %2;" : "=l"(r) : "l"(a), "l"(b)); return r;
}
__device__ __forceinline__ ull f32x2_fma(ull a, ull b, ull c) {
    ull r; asm("fma.rn.f32x2 %0, %1, %2, %3;" : "=l"(r) : "l"(a), "l"(b), "l"(c)); return r;
}
__device__ __forceinline__ ull f32x2_abs(ull a) { return a & 0x7FFFFFFF7FFFFFFFULL; }
__device__ __forceinline__ ull f32x2_dup(float v) {
    unsigned u = __float_as_uint(v); return ((ull)u << 32) | (ull)u;
}
__device__ __forceinline__ float f32x2_lo(ull a) { return __uint_as_float((unsigned)a); }
__device__ __forceinline__ float f32x2_hi(ull a) { return __uint_as_float((unsigned)(a >> 32)); }

// ---------------------------------------------------------------------------
// Kernel 1: f_input = features @ FC (+ Spart partials + Lw).
// Tile 32(M)x64(N), 128 threads, acc[4][2]. grid (4, 24) = 96 blocks.
// ---------------------------------------------------------------------------
__global__ void k_fin(const float* __restrict__ feat, const float* __restrict__ FCm,
                      const float* __restrict__ lin_w) {
    __shared__ ull   sa2[32 * 32];   // feat pairs (8KB)
    __shared__ float sb[32 * 64];    // FC rows (8KB)

    const int tid = threadIdx.x;     // 128
    const int tx = tid & 15;
    const int ty = tid >> 4;         // 0..7
    const int j0 = blockIdx.x * 64;
    const int i0 = blockIdx.y * 32;

    ull acc[4][2];
    #pragma unroll
    for (int r = 0; r < 4; r++) { acc[r][0] = 0ull; acc[r][1] = 0ull; }

    for (int s = 0; s < 8; s++) {
        const int k0 = s * 32;
        #pragma unroll
        for (int q = 0; q < 8; q++) {
            int idx = tid + q * 128;
            sa2[idx] = f32x2_dup(feat[(i0 + (idx >> 5)) * CV + k0 + (idx & 31)]);
        }
        #pragma unroll
        for (int q = 0; q < 4; q++) {
            int i4 = tid + q * 128;
            *(float4*)&sb[(i4 >> 4) * 64 + (i4 & 15) * 4] =
                *(const float4*)&FCm[(k0 + (i4 >> 4)) * CV + j0 + (i4 & 15) * 4];
        }
        __syncthreads();

        #pragma unroll 8
        for (int kc = 0; kc < 32; kc++) {
            ull a_[4], b_[2];
            #pragma unroll
            for (int r = 0; r < 4; r++) a_[r] = sa2[(ty + 8 * r) * 32 + kc];
            #pragma unroll
            for (int m = 0; m < 2; m++) b_[m] = *(const ull*)&sb[kc * 64 + 2 * (tx + 16 * m)];
            #pragma unroll
            for (int r = 0; r < 4; r++)
                #pragma unroll
                for (int m = 0; m < 2; m++)
                    acc[r][m] = f32x2_fma(a_[r], b_[m], acc[r][m]);
        }
        __syncthreads();
    }

    const float lw00 = lin_w[j0 + 2 * tx],      lw01 = lin_w[j0 + 2 * tx + 1];
    const float lw10 = lin_w[j0 + 2 * tx + 32], lw11 = lin_w[j0 + 2 * tx + 33];

    #pragma unroll
    for (int r = 0; r < 4; r++) {
        int i = i0 + ty + 8 * r;
        #pragma unroll
        for (int m = 0; m < 2; m++)
            *(ull*)&g_fin[i * CV + j0 + 2 * (tx + 16 * m)] = acc[r][m];
        float s = f32x2_lo(acc[r][0]) * lw00 + f32x2_hi(acc[r][0]) * lw01
                + f32x2_lo(acc[r][1]) * lw10 + f32x2_hi(acc[r][1]) * lw11;
        #pragma unroll
        for (int off = 8; off > 0; off >>= 1)
            s += __shfl_down_sync(0xffffffffu, s, off, 16);
        if (tx == 0) g_Spart[blockIdx.x * NV + i] = s;
    }

    if (blockIdx.x == 0 && blockIdx.y == 0) {
        __syncthreads();
        sb[tid] = lin_w[tid] + lin_w[tid + 128];
        __syncthreads();
        #pragma unroll
        for (int s = 64; s > 0; s >>= 1) {
            if (tid < s) sb[tid] += sb[tid + s];
            __syncthreads();
        }
        if (tid == 0) g_Lw = sb[0];
    }
}

// ---------------------------------------------------------------------------
// Kernel 2: scores + per-block softmax stats. 64x64 tile, 256 threads,
// acc[4][4], 4 channels per iteration via LDS.128 (SROW=260 keeps rows
// 16B-aligned; bank residues 4*tx..4*tx+3 per phase -> conflict-free).
// score(i,j) = leaky( 0.6*(P_i+Q_j) + lin_b + sum_c 0.4*lw[c]*|u_i[c]+v_j[c]| )
// ---------------------------------------------------------------------------
#define SROW 260
#define SMEM_SCORES ((2 * 64 * SROW + 256 + 2 * 192 + 16) * 4)

__global__ void __launch_bounds__(256, 1) k_scores(
        const float* __restrict__ coord,
        const float* __restrict__ fc_w, const float* __restrict__ fc_b,
        const float* __restrict__ sc_w, const float* __restrict__ sc_b,
        const float* __restrict__ lin_w, const float* __restrict__ lin_b) {
    extern __shared__ float smem[];
    float* su  = smem;                        // [64][SROW]
    float* sv  = smem + 64 * SROW;            // [64][SROW]
    float* slw = smem + 2 * 64 * SROW;        // [256]
    float* scu = slw + 256;                   // [64*3]
    float* scv = scu + 192;                   // [64*3]

    const int tid = threadIdx.x;
    const int tx = tid & 15;
    const int ty = tid >> 4;
    const int i0 = blockIdx.y * 64;
    const int j0 = blockIdx.x * 64;

    const float w0 = fc_w[0], w1 = fc_w[1], bf = fc_b[0];

    {
        const int r = tid >> 2, l4 = tid & 3;
        const float4* gi = (const float4*)&g_fin[(i0 + r) * CV];
        const float4* gj = (const float4*)&g_fin[(j0 + r) * CV];
        float* sur = &su[r * SROW];
        float* svr = &sv[r * SROW];
        #pragma unroll
        for (int q = 0; q < 16; q++) {
            float4 a = gi[l4 + q * 4];
            float4 b = gj[l4 + q * 4];
            int o = (l4 + q * 4) * 4;
            sur[o]     = w0 * a.x; sur[o + 1] = w0 * a.y;
            sur[o + 2] = w0 * a.z; sur[o + 3] = w0 * a.w;
            svr[o]     = fmaf(w1, b.x, bf); svr[o + 1] = fmaf(w1, b.y, bf);
            svr[o + 2] = fmaf(w1, b.z, bf); svr[o + 3] = fmaf(w1, b.w, bf);
        }
        slw[tid] = 0.4f * lin_w[tid];
        if (tid < 192) {
            int rr = tid / 3, k = tid - rr * 3;
            scu[tid] = sc_w[0] * coord[(i0 + rr) * 3 + k];
            scv[tid] = fmaf(sc_w[1], coord[(j0 + rr) * 3 + k], sc_b[0]);
        }
    }
    __syncthreads();

    const float* sup[4];
    const float* svp[4];
    #pragma unroll
    for (int k = 0; k < 4; k++) sup[k] = &su[(ty + 16 * k) * SROW];
    #pragma unroll
    for (int m = 0; m < 4; m++) svp[m] = &sv[(tx + 16 * m) * SROW];

    ull acc[4][4];
    #pragma unroll
    for (int k = 0; k < 4; k++)
        #pragma unroll
        for (int m = 0; m < 4; m++) acc[k][m] = 0ull;

    #pragma unroll 2
    for (int cc = 0; cc < CV; cc += 4) {
        ulonglong2 w4 = *(const ulonglong2*)&slw[cc];
        ulonglong2 a4[4], b4[4];
        #pragma unroll
        for (int k = 0; k < 4; k++) a4[k] = *(const ulonglong2*)&sup[k][cc];
        #pragma unroll
        for (int m = 0; m < 4; m++) b4[m] = *(const ulonglong2*)&svp[m][cc];
        #pragma unroll
        for (int k = 0; k < 4; k++)
            #pragma unroll
            for (int m = 0; m < 4; m++) {
                ull t0 = f32x2_abs(f32x2_add(a4[k].x, b4[m].x));
                acc[k][m] = f32x2_fma(w4.x, t0, acc[k][m]);
                ull t1 = f32x2_abs(f32x2_add(a4[k].y, b4[m].y));
                acc[k][m] = f32x2_fma(w4.y, t1, acc[k][m]);
            }
    }

    const float lb  = lin_b[0];
    const float Lw  = g_Lw;
    const float lc0 = lin_w[CV], lc1 = lin_w[CV + 1], lc2 = lin_w[CV + 2];
    const float base0 = fmaf(0.6f * bf, Lw, lb);

    float Si[4], Sj[4];
    #pragma unroll
    for (int k = 0; k < 4; k++) {
        int i = i0 + ty + 16 * k;
        Si[k] = (g_Spart[i] + g_Spart[NV + i]) + (g_Spart[2 * NV + i] + g_Spart[3 * NV + i]);
    }
    #pragma unroll
    for (int m = 0; m < 4; m++) {
        int j = j0 + tx + 16 * m;
        Sj[m] = (g_Spart[j] + g_Spart[NV + j]) + (g_Spart[2 * NV + j] + g_Spart[3 * NV + j]);
    }

    #pragma unroll
    for (int k = 0; k < 4; k++) {
        int ir = ty + 16 * k;
        float cu0 = scu[ir * 3], cu1 = scu[ir * 3 + 1], cu2 = scu[ir * 3 + 2];
        float val[4];
        #pragma unroll
        for (int m = 0; m < 4; m++) {
            int jr = tx + 16 * m;
            float t0 = cu0 + scv[jr * 3];
            float t1 = cu1 + scv[jr * 3 + 1];
            float t2 = cu2 + scv[jr * 3 + 2];
            float ct = lc0 * fmaf(0.4f, fabsf(t0), 0.6f * t0)
                     + lc1 * fmaf(0.4f, fabsf(t1), 0.6f * t1)
                     + lc2 * fmaf(0.4f, fabsf(t2), 0.6f * t2);
            float s = fmaf(0.6f, fmaf(w0, Si[k], w1 * Sj[m]), base0) + ct
                      + f32x2_lo(acc[k][m]) + f32x2_hi(acc[k][m]);
            val[m] = fmaxf(s, 0.2f * s);   // leaky(0.2)
            g_att[(i0 + ir) * NV + (j0 + jr)] = val[m];
        }
        float mx = fmaxf(fmaxf(val[0], val[1]), fmaxf(val[2], val[3]));
        #pragma unroll
        for (int o = 1; o < 16; o <<= 1)
            mx = fmaxf(mx, __shfl_xor_sync(0xffffffffu, mx, o));
        float se = __expf(val[0] - mx) + __expf(val[1] - mx)
                 + __expf(val[2] - mx) + __expf(val[3] - mx);
        #pragma unroll
        for (int o = 1; o < 16; o <<= 1)
            se += __shfl_xor_sync(0xffffffffu, se, o);
        if (tx == 0) {
            g_bm[blockIdx.x][i0 + ir] = mx;
            g_bs[blockIdx.x][i0 + ir] = se;
        }
    }
}

// ---------------------------------------------------------------------------
// Kernel 3: out partials = exp(scores - rowmax) @ f_input, split-K (8 ways).
// Tile 32(M)x128(N), 128 threads, acc[4][4]. grid (2, 24, 8) = 384 blocks.
// ---------------------------------------------------------------------------
__global__ void k_out_mm() {
    __shared__ ull   sa2[32 * 32];    // exp(att - m) pairs (8KB)
    __shared__ float sb[32 * 128];    // f_input rows (16KB)
    __shared__ float sm_m[32];        // row maxima

    const int tid = threadIdx.x;      // 128
    const int tx = tid & 15;
    const int ty = tid >> 4;          // 0..7
    const int j0 = blockIdx.x * 128;
    const int i0 = blockIdx.y * 32;
    const int kbase = blockIdx.z * 96;

    if (tid < 32) {
        float m = -1e30f;
        #pragma unroll
        for (int b = 0; b < 12; b++) m = fmaxf(m, g_bm[b][i0 + tid]);
        sm_m[tid] = m;
    }
    __syncthreads();

    ull acc[4][4];
    #pragma unroll
    for (int r = 0; r < 4; r++)
        #pragma unroll
        for (int m = 0; m < 4; m++) acc[r][m] = 0ull;

    for (int s = 0; s < 3; s++) {
        const int k0 = kbase + s * 32;
        #pragma unroll
        for (int q = 0; q < 8; q++) {
            int idx = tid + q * 128;
            int r = idx >> 5;
            sa2[idx] = f32x2_dup(__expf(g_att[(i0 + r) * NV + k0 + (idx & 31)] - sm_m[r]));
        }
        #pragma unroll
        for (int q = 0; q < 8; q++) {
            int i4 = tid + q * 128;
            *(float4*)&sb[(i4 >> 5) * 128 + (i4 & 31) * 4] =
                *(const float4*)&g_fin[(k0 + (i4 >> 5)) * CV + j0 + (i4 & 31) * 4];
        }
        __syncthreads();

        #pragma unroll 8
        for (int kc = 0; kc < 32; kc++) {
            ull a_[4], b_[4];
            #pragma unroll
            for (int r = 0; r < 4; r++) a_[r] = sa2[(ty + 8 * r) * 32 + kc];
            #pragma unroll
            for (int m = 0; m < 4; m++) b_[m] = *(const ull*)&sb[kc * 128 + 2 * (tx + 16 * m)];
            #pragma unroll
            for (int r = 0; r < 4; r++)
                #pragma unroll
                for (int m = 0; m < 4; m++)
                    acc[r][m] = f32x2_fma(a_[r], b_[m], acc[r][m]);
        }
        __syncthreads();
    }

    float* dst = g_op[blockIdx.z];
    #pragma unroll
    for (int r = 0; r < 4; r++) {
        int i = i0 + ty + 8 * r;
        #pragma unroll
        for (int m = 0; m < 4; m++)
            *(ull*)&dst[i * CV + j0 + 2 * (tx + 16 * m)] = acc[r][m];
    }
}

// ---------------------------------------------------------------------------
// Kernel 4: reduce 8 out partials, compute 1/rowsum, ELU. Warp-per-row.
// grid 96, block 256.
// ---------------------------------------------------------------------------
__global__ void k_outred(float* __restrict__ out) {
    const int w = threadIdx.x >> 5, lane = threadIdx.x & 31;
    const int row = blockIdx.x * 8 + w;
    const int c0 = row * CV + lane * 8;

    float m = -1e30f;
    #pragma unroll
    for (int b = 0; b < 12; b++) m = fmaxf(m, g_bm[b][row]);
    float ssum = 0.f;
    #pragma unroll
    for (int b = 0; b < 12; b++) ssum += g_bs[b][row] * __expf(g_bm[b][row] - m);
    const float inv = 1.0f / ssum;

    float4 s0 = make_float4(0.f, 0.f, 0.f, 0.f);
    float4 s1 = make_float4(0.f, 0.f, 0.f, 0.f);
    #pragma unroll
    for (int p = 0; p < 8; p++) {
        float4 a = *(const float4*)&g_op[p][c0];
        float4 b = *(const float4*)&g_op[p][c0 + 4];
        s0.x += a.x; s0.y += a.y; s0.z += a.z; s0.w += a.w;
        s1.x += b.x; s1.y += b.y; s1.z += b.z; s1.w += b.w;
    }
    s0.x *= inv; s0.y *= inv; s0.z *= inv; s0.w *= inv;
    s1.x *= inv; s1.y *= inv; s1.z *= inv; s1.w *= inv;
    s0.x = (s0.x > 0.f) ? s0.x : (__expf(s0.x) - 1.f);
    s0.y = (s0.y > 0.f) ? s0.y : (__expf(s0.y) - 1.f);
    s0.z = (s0.z > 0.f) ? s0.z : (__expf(s0.z) - 1.f);
    s0.w = (s0.w > 0.f) ? s0.w : (__expf(s0.w) - 1.f);
    s1.x = (s1.x > 0.f) ? s1.x : (__expf(s1.x) - 1.f);
    s1.y = (s1.y > 0.f) ? s1.y : (__expf(s1.y) - 1.f);
    s1.z = (s1.z > 0.f) ? s1.z : (__expf(s1.z) - 1.f);
    s1.w = (s1.w > 0.f) ? s1.w : (__expf(s1.w) - 1.f);
    *(float4*)&out[c0]     = s0;
    *(float4*)&out[c0 + 4] = s1;
}

// ---------------------------------------------------------------------------
extern "C" void kernel_launch(void* const* d_in, const int* in_sizes, int n_in,
                              void* d_out, int out_size) {
    const float* feat  = (const float*)d_in[0];
    const float* coord = (const float*)d_in[1];
    // d_in[2] = adj (unused by forward)
    const float* FCm   = (const float*)d_in[3];
    const float* fc_w  = (const float*)d_in[4];
    const float* fc_b  = (const float*)d_in[5];
    const float* sc_w  = (const float*)d_in[6];
    const float* sc_b  = (const float*)d_in[7];
    const float* lin_w = (const float*)d_in[8];
    const float* lin_b = (const float*)d_in[9];
    float* out = (float*)d_out;

    cudaFuncSetAttribute(k_scores, cudaFuncAttributeMaxDynamicSharedMemorySize,
                         SMEM_SCORES);

    k_fin<<<dim3(4, 24), 128>>>(feat, FCm, lin_w);
    k_scores<<<dim3(12, 12), 256, SMEM_SCORES>>>(coord, fc_w, fc_b, sc_w, sc_b, lin_w, lin_b);
    k_out_mm<<<dim3(2, 24, 8), 128>>>();
    k_outred<<<96, 256>>>(out);
}